// round 8
// baseline (speedup 1.0000x reference)
#include <cuda_runtime.h>
#include <math.h>

#define NQ   12
#define DIM  4096
#define NL   4
#define TPB  512

// Fused RZ*RY*RX gate per (layer, wire): 2 float4 = row0 (u00r,u00i,u01r,u01i), row1 (u10r,u10i,u11r,u11i)
__device__ float4 g_U4[NL * NQ * 2];

__global__ void precompute_gates(const float* __restrict__ qw) {
    int id = threadIdx.x;
    if (id >= NL * NQ) return;
    float a = qw[3 * id + 0];
    float b = qw[3 * id + 1];
    float g = qw[3 * id + 2];
    float cA = cosf(0.5f * a), sA = sinf(0.5f * a);
    float cB = cosf(0.5f * b), sB = sinf(0.5f * b);
    float cC = cosf(0.5f * g), sC = sinf(0.5f * g);
    float m00r =  cB * cA, m00i =  sB * sA;
    float m01r = -sB * cA, m01i = -cB * sA;
    float m10r =  sB * cA, m10i = -cB * sA;
    float m11r =  cB * cA, m11i = -sB * sA;
    float* o = (float*)&g_U4[id * 2];
    o[0] = cC * m00r + sC * m00i;  o[1] = cC * m00i - sC * m00r;
    o[2] = cC * m01r + sC * m01i;  o[3] = cC * m01i - sC * m01r;
    o[4] = cC * m10r - sC * m10i;  o[5] = cC * m10i + sC * m10r;
    o[6] = cC * m11r - sC * m11i;  o[7] = cC * m11i + sC * m11r;
}

__device__ __forceinline__ float2 cmul(float2 a, float2 b) {
    return make_float2(a.x * b.x - a.y * b.y, a.x * b.y + a.y * b.x);
}

// Apply fused 1q gate on register-slot bit bb (8-amp tile -> 4 pairs)
#define APPLY_GATE3(bb, ua, ub) do {                                         \
    _Pragma("unroll")                                                        \
    for (int m = 0; m < 4; m++) {                                            \
        const int lowm = (1 << (bb)) - 1;                                    \
        const int i0 = ((m & ~lowm) << 1) | (m & lowm);                      \
        const int i1 = i0 | (1 << (bb));                                     \
        float2 v0 = r[i0], v1 = r[i1];                                       \
        float2 n0, n1;                                                       \
        n0.x = ua.x*v0.x - ua.y*v0.y + ua.z*v1.x - ua.w*v1.y;                \
        n0.y = ua.x*v0.y + ua.y*v0.x + ua.z*v1.y + ua.w*v1.x;                \
        n1.x = ub.x*v0.x - ub.y*v0.y + ub.z*v1.x - ub.w*v1.y;                \
        n1.y = ub.x*v0.y + ub.y*v0.x + ub.z*v1.y + ub.w*v1.x;                \
        r[i0] = n0; r[i1] = n1;                                              \
    }                                                                        \
} while (0)

__global__ __launch_bounds__(TPB, 2) void qsim(const float* __restrict__ x,
                                               const float* __restrict__ dw,
                                               const float* __restrict__ db,
                                               float* __restrict__ out) {
    __shared__ float2 s_psi[DIM];          // 32 KB state (per-pass GF(2)-swizzled layouts)
    __shared__ float4 s_U4[NL * NQ * 2];   // fused gates
    __shared__ float  s_x[NQ];
    __shared__ float2 s_w[NQ][2];          // per-BIT-POSITION local 2-vectors (layer 0 folded)
    __shared__ float  s_scalar[2];
    __shared__ float  s_red[16 * NQ];
    __shared__ float  s_q[NQ];

    const int t = threadIdx.x;             // 9 bits
    const int bidx = blockIdx.x;

    for (int i = t; i < NL * NQ * 2; i += TPB) s_U4[i] = g_U4[i];
    if (t < NQ) s_x[t] = x[bidx * NQ + t];
    __syncthreads();

    if (t == 0) {
        float ss = 0.f, ma = 0.f;
        #pragma unroll
        for (int w = 0; w < NQ; w++) {
            float v = s_x[w];
            ss += v * v;
            ma = fmaxf(ma, fabsf(v));
        }
        float rr = rsqrtf(fmaxf(ss, 1e-12f));
        s_scalar[0] = rr;
        s_scalar[1] = ma * rr;
    }
    __syncthreads();
    if (t < NQ) {
        float rr = s_scalar[0], m = s_scalar[1];
        float ang = 3.14159265358979f * (s_x[t] * rr) / (m + 1e-8f);
        float c = cosf(0.5f * ang);
        float s = sinf(0.5f * ang);
        // fuse layer-0 gate for wire t into the local 2-vector
        float4 ua = s_U4[t * 2], ub = s_U4[t * 2 + 1];
        int p = 11 - t;                    // wire t lives at bit position 11-t
        s_w[p][0] = make_float2(ua.x * c + ua.z * s, ua.y * c + ua.w * s);
        s_w[p][1] = make_float2(ub.x * c + ub.z * s, ub.y * c + ub.w * s);
    }
    __syncthreads();

    float2 r[8];                           // 8 amps per thread

    // ---------- init in HIGH3 ownership: L = (s<<9)|t ; store layoutD (identity)
    {
        float2 ct = s_w[0][t & 1];
        #pragma unroll
        for (int p = 1; p < 9; p++) ct = cmul(ct, s_w[p][(t >> p) & 1]);
        float2 m01[4];
        #pragma unroll
        for (int a = 0; a < 4; a++)
            m01[a] = cmul(ct, cmul(s_w[9][a & 1], s_w[10][(a >> 1) & 1]));
        #pragma unroll
        for (int s = 0; s < 8; s++) r[s] = cmul(m01[s & 3], s_w[11][s >> 2]);
        #pragma unroll
        for (int s = 0; s < 8; s++) s_psi[t | (s << 9)] = r[s];
    }
    __syncthreads();

    #pragma unroll 1
    for (int layer = 1; layer < NL; layer++) {
        // ---------- P0: reg bits {9,10,11} = wires 2,1,0. Load layoutD w/ CNOT perm folded.
        {
            int base0 = t ^ (t >> 1) ^ ((t & 1) ? 0xC00 : 0);
            #pragma unroll
            for (int s = 0; s < 8; s++)
                r[s] = s_psi[base0 ^ ((s << 9) ^ (s << 8))];
        }
        {
            const float4 a2 = s_U4[(layer * NQ + 2) * 2], b2 = s_U4[(layer * NQ + 2) * 2 + 1];
            APPLY_GATE3(0, a2, b2);   // s-bit 0 = L bit 9  = wire 2
            const float4 a1 = s_U4[(layer * NQ + 1) * 2], b1 = s_U4[(layer * NQ + 1) * 2 + 1];
            APPLY_GATE3(1, a1, b1);   // s-bit 1 = L bit 10 = wire 1
            const float4 a0 = s_U4[(layer * NQ + 0) * 2], b0 = s_U4[(layer * NQ + 0) * 2 + 1];
            APPLY_GATE3(2, a0, b0);   // s-bit 2 = L bit 11 = wire 0
        }
        __syncthreads();
        {
            int baseA = (t & ~7) | ((t ^ (t >> 4)) & 7);
            #pragma unroll
            for (int s = 0; s < 8; s++) s_psi[baseA | (s << 9)] = r[s];
        }
        __syncthreads();

        // ---------- P1: reg bits {0,1,2} = wires 11,10,9. Load layoutA.
        {
            int base1 = (t << 3) | ((t >> 1) & 7);
            #pragma unroll
            for (int s = 0; s < 8; s++) r[s] = s_psi[base1 ^ s];
        }
        {
            const float4 a11 = s_U4[(layer * NQ + 11) * 2], b11 = s_U4[(layer * NQ + 11) * 2 + 1];
            APPLY_GATE3(0, a11, b11);
            const float4 a10 = s_U4[(layer * NQ + 10) * 2], b10 = s_U4[(layer * NQ + 10) * 2 + 1];
            APPLY_GATE3(1, a10, b10);
            const float4 a9  = s_U4[(layer * NQ +  9) * 2], b9  = s_U4[(layer * NQ +  9) * 2 + 1];
            APPLY_GATE3(2, a9, b9);
        }
        __syncthreads();
        {
            int baseS1 = (t & 7) | (((t >> 3) & 1) << 3) | ((t & 7) << 4) | (((t >> 4) & 31) << 7);
            #pragma unroll
            for (int s = 0; s < 8; s++) s_psi[baseS1 ^ s] = r[s];
        }
        __syncthreads();

        // ---------- P2: reg bits {3,4,5} = wires 8,7,6. Load layoutB.
        {
            int base2 = (t & 7) | (((t >> 3) & 1) << 3) | (((t >> 4) & 31) << 7);
            #pragma unroll
            for (int s = 0; s < 8; s++) r[s] = s_psi[base2 ^ (s | (s << 4))];
        }
        {
            const float4 a8 = s_U4[(layer * NQ + 8) * 2], b8 = s_U4[(layer * NQ + 8) * 2 + 1];
            APPLY_GATE3(0, a8, b8);
            const float4 a7 = s_U4[(layer * NQ + 7) * 2], b7 = s_U4[(layer * NQ + 7) * 2 + 1];
            APPLY_GATE3(1, a7, b7);
            const float4 a6 = s_U4[(layer * NQ + 6) * 2], b6 = s_U4[(layer * NQ + 6) * 2 + 1];
            APPLY_GATE3(2, a6, b6);
        }
        __syncthreads();
        {
            int baseS2 = (t & 7) | (((t >> 3) & 1) << 3) | (((t >> 3) & 1) << 6) | (((t >> 4) & 31) << 7);
            #pragma unroll
            for (int s = 0; s < 8; s++) s_psi[baseS2 ^ (s << 3)] = r[s];
        }
        __syncthreads();

        // ---------- P3: reg bits {6,7,8} = wires 5,4,3. Load layoutC.
        {
            int base3 = (t & 63) | ((t >> 6) << 9);
            #pragma unroll
            for (int s = 0; s < 8; s++) r[s] = s_psi[base3 ^ ((s << 6) | ((s & 1) << 3))];
        }
        {
            const float4 a5 = s_U4[(layer * NQ + 5) * 2], b5 = s_U4[(layer * NQ + 5) * 2 + 1];
            APPLY_GATE3(0, a5, b5);
            const float4 a4 = s_U4[(layer * NQ + 4) * 2], b4 = s_U4[(layer * NQ + 4) * 2 + 1];
            APPLY_GATE3(1, a4, b4);
            const float4 a3 = s_U4[(layer * NQ + 3) * 2], b3 = s_U4[(layer * NQ + 3) * 2 + 1];
            APPLY_GATE3(2, a3, b3);
        }
        if (layer < NL - 1) {
            __syncthreads();
            int base3 = (t & 63) | ((t >> 6) << 9);
            #pragma unroll
            for (int s = 0; s < 8; s++) s_psi[base3 | (s << 6)] = r[s];
            __syncthreads();
        }
        // layer-boundary CNOT ring folds into next P0 load / epilogue index map
    }

    // ---------- epilogue: final ring perm via inverse index map, then <Z_w>
    // r holds MID3b ownership: pre-ring logical L = (t&63) | (s<<6) | ((t>>6)<<9)
    int L1 = (t & 63) | (((t >> 6) & 7) << 9);
    int xt = L1 ^ ((__popc(L1) & 1) ? 0xC00 : 0);
    xt ^= xt >> 1; xt ^= xt >> 2; xt ^= xt >> 4; xt ^= xt >> 8;

    float z[NQ];
    #pragma unroll
    for (int w = 0; w < NQ; w++) z[w] = 0.f;
    #pragma unroll
    for (int s = 0; s < 8; s++) {
        int xs = (s << 6) ^ ((__popc(s) & 1) ? 0xC00 : 0);
        xs ^= xs >> 1; xs ^= xs >> 2; xs ^= xs >> 4; xs ^= xs >> 8;
        int j = xt ^ xs;                    // final logical basis index
        float2 v = r[s];
        float pr = v.x * v.x + v.y * v.y;
        #pragma unroll
        for (int w = 0; w < NQ; w++)
            z[w] += ((j >> (11 - w)) & 1) ? -pr : pr;
    }

    const int lane = t & 31, warp = t >> 5;   // 16 warps
    #pragma unroll
    for (int w = 0; w < NQ; w++) {
        float v = z[w];
        #pragma unroll
        for (int off = 16; off; off >>= 1)
            v += __shfl_down_sync(0xffffffffu, v, off);
        if (lane == 0) s_red[warp * NQ + w] = v;
    }
    __syncthreads();
    if (t < NQ) {
        float qv = 0.f;
        #pragma unroll
        for (int wp = 0; wp < 16; wp++) qv += s_red[wp * NQ + t];
        s_q[t] = qv;
    }
    __syncthreads();
    if (t < NQ) {
        float acc = db[t];
        #pragma unroll
        for (int w = 0; w < NQ; w++) acc += s_q[w] * dw[w * NQ + t];
        out[bidx * NQ + t] = tanhf(acc);
    }
}

extern "C" void kernel_launch(void* const* d_in, const int* in_sizes, int n_in,
                              void* d_out, int out_size) {
    const float* x  = (const float*)d_in[0];
    const float* qw = (const float*)d_in[1];
    const float* dw = (const float*)d_in[2];
    const float* db = (const float*)d_in[3];
    float* out = (float*)d_out;

    int batch = in_sizes[0] / NQ;

    precompute_gates<<<1, 64>>>(qw);
    qsim<<<batch, TPB>>>(x, dw, db, out);
}

// round 9
// speedup vs baseline: 1.2626x; 1.2626x over previous
#include <cuda_runtime.h>
#include <math.h>

#define NQ   12
#define DIM  4096
#define NL   4
#define TPB  256

// SU(2)-compressed fused RZ*RY*RX gate per (layer, wire): row0 only,
// (u00r, u00i, u01r, u01i). Row1 = (-conj(u01), conj(u00)) derived in-kernel.
__device__ float4 g_U4[NL * NQ];

__global__ void precompute_gates(const float* __restrict__ qw) {
    int id = threadIdx.x;
    if (id >= NL * NQ) return;
    float a = qw[3 * id + 0];
    float b = qw[3 * id + 1];
    float g = qw[3 * id + 2];
    float cA = cosf(0.5f * a), sA = sinf(0.5f * a);
    float cB = cosf(0.5f * b), sB = sinf(0.5f * b);
    float cC = cosf(0.5f * g), sC = sinf(0.5f * g);
    float m00r =  cB * cA, m00i =  sB * sA;
    float m01r = -sB * cA, m01i = -cB * sA;
    // row0 of U = e^{-iC} * (RY*RX row0)
    float u00r = cC * m00r + sC * m00i, u00i = cC * m00i - sC * m00r;
    float u01r = cC * m01r + sC * m01i, u01i = cC * m01i - sC * m01r;
    g_U4[id] = make_float4(u00r, u00i, u01r, u01i);
}

// phys address (element index) of logical amp under layout "active = {8..11}"
__device__ __forceinline__ int physHIGH(int x) {
    return ((x & 0xFF) << 4) | (((x >> 8) ^ x) & 15);
}

__device__ __forceinline__ float2 cmul(float2 a, float2 b) {
    return make_float2(a.x * b.x - a.y * b.y, a.x * b.y + a.y * b.x);
}

// Apply fused SU(2) gate on register-slot bit bb; ua = (u00r,u00i,u01r,u01i).
// Row1 derived: u10 = (-u01r, u01i), u11 = (u00r, -u00i). Negations fold into
// FFMA operand modifiers (free).
#define APPLY_GATE(bb, ua) do {                                              \
    _Pragma("unroll")                                                        \
    for (int m = 0; m < 8; m++) {                                            \
        const int lowm = (1 << (bb)) - 1;                                    \
        const int i0 = ((m & ~lowm) << 1) | (m & lowm);                      \
        const int i1 = i0 | (1 << (bb));                                     \
        float2 v0 = r[i0], v1 = r[i1];                                       \
        float2 n0, n1;                                                       \
        n0.x =  ua.x*v0.x - ua.y*v0.y + ua.z*v1.x - ua.w*v1.y;               \
        n0.y =  ua.x*v0.y + ua.y*v0.x + ua.z*v1.y + ua.w*v1.x;               \
        n1.x = -ua.z*v0.x - ua.w*v0.y + ua.x*v1.x + ua.y*v1.y;               \
        n1.y = -ua.z*v0.y + ua.w*v0.x + ua.x*v1.y - ua.y*v1.x;               \
        r[i0] = n0; r[i1] = n1;                                              \
    }                                                                        \
} while (0)

__global__ __launch_bounds__(TPB, 3) void qsim(const float* __restrict__ x,
                                               const float* __restrict__ dw,
                                               const float* __restrict__ db,
                                               float* __restrict__ out) {
    __shared__ float2 s_psi[DIM];          // 32 KB state (swizzled layouts)
    __shared__ float4 s_U4[NL * NQ];       // SU(2)-compressed gates (768 B)
    __shared__ float  s_x[NQ];
    __shared__ float2 s_w[NQ][2];          // per-BIT-POSITION local 2-vectors (layer 0 folded)
    __shared__ float  s_scalar[2];
    __shared__ float  s_red[8 * NQ];
    __shared__ float  s_q[NQ];

    const int t = threadIdx.x;
    const int bidx = blockIdx.x;

    for (int i = t; i < NL * NQ; i += TPB) s_U4[i] = g_U4[i];
    if (t < NQ) s_x[t] = x[bidx * NQ + t];
    __syncthreads();

    if (t == 0) {
        float ss = 0.f, ma = 0.f;
        #pragma unroll
        for (int w = 0; w < NQ; w++) {
            float v = s_x[w];
            ss += v * v;
            ma = fmaxf(ma, fabsf(v));
        }
        float rr = rsqrtf(fmaxf(ss, 1e-12f));
        s_scalar[0] = rr;
        s_scalar[1] = ma * rr;
    }
    __syncthreads();
    if (t < NQ) {
        float rr = s_scalar[0], m = s_scalar[1];
        float ang = 3.14159265358979f * (s_x[t] * rr) / (m + 1e-8f);
        float c = cosf(0.5f * ang);
        float s = sinf(0.5f * ang);
        // fuse layer-0 gate for wire t into the local 2-vector
        float4 ua = s_U4[t];
        int p = 11 - t;                    // wire t lives at bit position 11-t
        // w0 = row0 . (c, s);  w1 = row1 . (c, s) with row1 = (-conj(u01), conj(u00))
        s_w[p][0] = make_float2( ua.x * c + ua.z * s,  ua.y * c + ua.w * s);
        s_w[p][1] = make_float2(-ua.z * c + ua.x * s,  ua.w * c - ua.y * s);
    }
    __syncthreads();

    float2 r[16];                          // 16 amps per thread (register tile)
    const int storeBase = (t << 4) | (t & 15);   // universal store: addr = storeBase ^ s

    // ---------- init in HIGH ownership: L = (s<<8)|t, amp = prod of w[bit]
    {
        float2 ct = s_w[0][t & 1];
        #pragma unroll
        for (int p = 1; p < 8; p++) ct = cmul(ct, s_w[p][(t >> p) & 1]);
        float2 m01[4], m23[4], ctm[4];
        #pragma unroll
        for (int a = 0; a < 4; a++) {
            m01[a] = cmul(s_w[8][a & 1],  s_w[9][(a >> 1) & 1]);
            m23[a] = cmul(s_w[10][a & 1], s_w[11][(a >> 1) & 1]);
        }
        #pragma unroll
        for (int a = 0; a < 4; a++) ctm[a] = cmul(ct, m01[a]);
        #pragma unroll
        for (int s = 0; s < 16; s++) r[s] = cmul(ctm[s & 3], m23[s >> 2]);
        #pragma unroll
        for (int s = 0; s < 16; s++) s_psi[storeBase ^ s] = r[s];
    }
    __syncthreads();

    #pragma unroll 1
    for (int layer = 1; layer < NL; layer++) {
        // ---------- pass MID: active positions {4..7}; load HIGH layout w/ CNOT perm folded
        {
            int T  = ((t & 0xF0) << 4) | (t & 15);
            int Xt = T ^ (T >> 1) ^ ((t & 1) ? 0xC00 : 0);
            int base = physHIGH(Xt & 0xFFF);
            #pragma unroll
            for (int s = 0; s < 16; s++) {
                int Xs = ((s << 4) ^ (s << 3)) & 0xFFF;
                r[s] = s_psi[base ^ physHIGH(Xs)];
            }
        }
        {
            const float4 a4 = s_U4[layer * NQ + 7];
            APPLY_GATE(0, a4);   // position 4 = wire 7
            const float4 a5 = s_U4[layer * NQ + 6];
            APPLY_GATE(1, a5);   // position 5 = wire 6
            const float4 a6 = s_U4[layer * NQ + 5];
            APPLY_GATE(2, a6);   // position 6 = wire 5
            const float4 a7 = s_U4[layer * NQ + 4];
            APPLY_GATE(3, a7);   // position 7 = wire 4
        }
        __syncthreads();               // all loads done before stores clobber
        #pragma unroll
        for (int s = 0; s < 16; s++) s_psi[storeBase ^ s] = r[s];
        __syncthreads();

        // ---------- pass LOW: active {0..3}; load from MID layout
        {
            int base = ((t & 0xF0) << 4) | (t & 15);
            #pragma unroll
            for (int s = 0; s < 16; s++) r[s] = s_psi[base ^ ((s << 4) | s)];
        }
        {
            const float4 a0 = s_U4[layer * NQ + 11];
            APPLY_GATE(0, a0);   // position 0 = wire 11
            const float4 a1 = s_U4[layer * NQ + 10];
            APPLY_GATE(1, a1);
            const float4 a2 = s_U4[layer * NQ + 9];
            APPLY_GATE(2, a2);
            const float4 a3 = s_U4[layer * NQ + 8];
            APPLY_GATE(3, a3);
        }
        __syncthreads();
        #pragma unroll
        for (int s = 0; s < 16; s++) s_psi[storeBase ^ s] = r[s];
        __syncthreads();

        // ---------- pass HIGH: active {8..11}; load from LOW layout
        {
            int base = t ^ ((t >> 4) & 15);
            #pragma unroll
            for (int s = 0; s < 16; s++) r[s] = s_psi[base ^ (s << 8)];
        }
        {
            const float4 a8 = s_U4[layer * NQ + 3];
            APPLY_GATE(0, a8);   // position 8 = wire 3
            const float4 a9 = s_U4[layer * NQ + 2];
            APPLY_GATE(1, a9);
            const float4 a10 = s_U4[layer * NQ + 1];
            APPLY_GATE(2, a10);
            const float4 a11 = s_U4[layer * NQ + 0];
            APPLY_GATE(3, a11);
        }
        if (layer < NL - 1) {
            __syncthreads();
            #pragma unroll
            for (int s = 0; s < 16; s++) s_psi[storeBase ^ s] = r[s];
            __syncthreads();
        }
        // layer-boundary CNOT ring folds into next MID load / epilogue index map
    }

    // ---------- epilogue: Walsh-transform form of the signed probability sums.
    // r holds HIGH ownership: pre-final-ring logical L = (s<<8) | t.
    // Sign of wire w (bit p=11-w) over s is a GF(2)-linear (Walsh) function:
    // ring-map basis images xs(1)=0x9FF, xs(2)=0xBFF, xs(4)=0xFFF, xs(8)=0x7FF
    // => masks: p=11 -> 7, p=10 -> 12, p=9 -> 14, p<=8 -> 15.
    float pr[16];
    #pragma unroll
    for (int s = 0; s < 16; s++) {
        float2 v = r[s];
        pr[s] = v.x * v.x + v.y * v.y;
    }
    float P[8], M[8];
    #pragma unroll
    for (int u = 0; u < 8; u++) {
        P[u] = pr[2 * u] + pr[2 * u + 1];
        M[u] = pr[2 * u] - pr[2 * u + 1];
    }
    float W15 = 0.f, W14 = 0.f, W12 = 0.f, W7 = 0.f;
    #pragma unroll
    for (int u = 0; u < 8; u++) {
        if (__popc(u) & 1)        { W15 -= M[u]; W14 -= P[u]; }
        else                      { W15 += M[u]; W14 += P[u]; }
        if (__popc(u >> 1) & 1)   W12 -= P[u]; else W12 += P[u];
        if (__popc(u & 3) & 1)    W7  -= M[u]; else W7  += M[u];
    }

    int xt = t ^ ((__popc(t) & 1) ? 0xC00 : 0);
    xt ^= xt >> 1; xt ^= xt >> 2; xt ^= xt >> 4; xt ^= xt >> 8;

    float z[NQ];
    #pragma unroll
    for (int w = 0; w < NQ; w++) {
        const int p = 11 - w;
        float Wv = (p == 11) ? W7 : (p == 10) ? W12 : (p == 9) ? W14 : W15;
        z[w] = ((xt >> p) & 1) ? -Wv : Wv;
    }

    const int lane = t & 31, warp = t >> 5;
    #pragma unroll
    for (int w = 0; w < NQ; w++) {
        float v = z[w];
        #pragma unroll
        for (int off = 16; off; off >>= 1)
            v += __shfl_down_sync(0xffffffffu, v, off);
        if (lane == 0) s_red[warp * NQ + w] = v;
    }
    __syncthreads();
    if (t < NQ) {
        float qv = 0.f;
        #pragma unroll
        for (int wp = 0; wp < 8; wp++) qv += s_red[wp * NQ + t];
        s_q[t] = qv;
    }
    __syncthreads();
    if (t < NQ) {
        float acc = db[t];
        #pragma unroll
        for (int w = 0; w < NQ; w++) acc += s_q[w] * dw[w * NQ + t];
        out[bidx * NQ + t] = tanhf(acc);
    }
}

extern "C" void kernel_launch(void* const* d_in, const int* in_sizes, int n_in,
                              void* d_out, int out_size) {
    const float* x  = (const float*)d_in[0];
    const float* qw = (const float*)d_in[1];
    const float* dw = (const float*)d_in[2];
    const float* db = (const float*)d_in[3];
    float* out = (float*)d_out;

    int batch = in_sizes[0] / NQ;

    precompute_gates<<<1, 64>>>(qw);
    qsim<<<batch, TPB>>>(x, dw, db, out);
}